// round 6
// baseline (speedup 1.0000x reference)
#include <cuda_runtime.h>

// PeriodicConvOp collapsed to a spatially-parameterized 3x3 conv:
//   out[b, co, 2hp+i, 2wp+j] =
//     sum_{cin,ky,kx} W[(g*8+o)*36 + cin*9 + ky*3 + kx]
//                     * x[b, cin, 2hp+gy+ky-1, 2wp+gx+kx-1]
//   g = co>>1, gy = g>>1, gx = g&1, o = ((co&1)<<2) | m, m = 2i+j
//
// Round-5 structure (R4 was latency/occupancy-bound: occ 21.4%, issue 40.5%):
//  - g is an OUTER sequential phase per warp: acc shrinks 64->16 regs, window
//    30 regs (5 rows x 3 cols for fixed gy,gx) -> ~90 regs -> 5 blocks/SM.
//  - Input pre-packed in smem as (v,v) 64-bit pairs: no pack MOVs in the loop,
//    window loads are wide LDS.
//  - Channel pairs (2g,2g+1) via packed fma.rn.f32x2; weights interleaved.
//  - Everything fully unrolled; 32-bit epilogue addressing.

#define CIN   4
#define COUT  8
#define HH    512
#define WW    512

#define TILE_H 16          // output rows per block
#define TILE_W 64          // output cols per block
#define SROWS  (TILE_H + 2)   // 18 input rows  (h0-1 .. h0+16)
#define SCOLS  (TILE_W + 2)   // 66 input cols  (w0-1 .. w0+64)
#define SX_PAIRS (CIN * SROWS * SCOLS)      // 4752 ull  (38016 B)

#define WPAIR_STRIDE 10    // float2 slots per (g,cin,m): 9 taps + 1 pad
#define SW_FLOATS (4 * CIN * 4 * WPAIR_STRIDE * 2)   // 1280 floats (5120 B)

#define NQ 2               // quad-rows per warp
#define NTHREADS 128       // 4 warps; block = 8 quad rows x 32 quad cols

typedef unsigned long long ull;

__device__ __forceinline__ ull pack2(float v) {
    ull r; asm("mov.b64 %0, {%1, %1};" : "=l"(r) : "f"(v)); return r;
}
__device__ __forceinline__ void unpack2(ull v, float& lo, float& hi) {
    asm("mov.b64 {%0, %1}, %2;" : "=f"(lo), "=f"(hi) : "l"(v));
}
__device__ __forceinline__ void fma2(ull& d, ull a, ull b) {
    asm("fma.rn.f32x2 %0, %1, %2, %0;" : "+l"(d) : "l"(a), "l"(b));
}

// One group phase. GX templated so window-load alignment pattern and all
// register-array indices are compile-time.
template<int GX>
__device__ __forceinline__ void do_group(
    const ull* __restrict__ sxp,      // packed input tile
    const float* __restrict__ sw2g,   // weights for this g: [cin][m][pairs]
    ull (&acc)[4][NQ],                // [m][q]
    int baserow,                      // 2*Q0 + gy
    int lane)
{
    #pragma unroll
    for (int cin = 0; cin < CIN; ++cin) {
        const ull* bp = sxp + cin * (SROWS * SCOLS) + baserow * SCOLS + 2 * lane;

        // 5 rows x 3 packed cols; win[2q+ky][kx]
        ull win[5][3];
        #pragma unroll
        for (int rr = 0; rr < 5; ++rr) {
            const ull* rowp = bp + rr * SCOLS;
            if (GX == 0) {
                ulonglong2 v = *reinterpret_cast<const ulonglong2*>(rowp);
                win[rr][0] = v.x; win[rr][1] = v.y; win[rr][2] = rowp[2];
            } else {
                win[rr][0] = rowp[1];
                ulonglong2 v = *reinterpret_cast<const ulonglong2*>(rowp + 2);
                win[rr][1] = v.x; win[rr][2] = v.y;
            }
        }

        #pragma unroll
        for (int m = 0; m < 4; ++m) {
            const ulonglong2* wp = reinterpret_cast<const ulonglong2*>(
                sw2g + (cin * 4 + m) * (2 * WPAIR_STRIDE));
            ull w[10];
            #pragma unroll
            for (int t = 0; t < 5; ++t) {
                ulonglong2 v = wp[t];
                w[2 * t] = v.x; w[2 * t + 1] = v.y;
            }
            #pragma unroll
            for (int q = 0; q < NQ; ++q)
                #pragma unroll
                for (int ky = 0; ky < 3; ++ky)
                    #pragma unroll
                    for (int kx = 0; kx < 3; ++kx)
                        fma2(acc[m][q], w[ky * 3 + kx], win[2 * q + ky][kx]);
        }
    }
}

__global__ void __launch_bounds__(NTHREADS, 5)
periodic_conv_kernel(const float* __restrict__ x,
                     const float* __restrict__ wt,
                     float* __restrict__ out)
{
    __shared__ __align__(16) ull   sxp[SX_PAIRS];
    __shared__ __align__(16) float sw2[SW_FLOATS];

    const int b   = blockIdx.z;
    const int h0  = blockIdx.y * TILE_H;
    const int w0  = blockIdx.x * TILE_W;
    const int tid = threadIdx.x;

    // ---- weights: channel-pair interleave. entry d = ((g*4+cin)*4+m)*10+t ----
    for (int d = tid; d < 4 * CIN * 4 * WPAIR_STRIDE; d += NTHREADS) {
        int t   = d % WPAIR_STRIDE;
        int r   = d / WPAIR_STRIDE;
        int m   = r & 3;  r >>= 2;
        int cin = r & 3;
        int g   = r >> 2;
        float lo = 0.f, hi = 0.f;
        if (t < 9) {
            lo = wt[(g * 8 + m    ) * 36 + cin * 9 + t];   // co = 2g   (o = m)
            hi = wt[(g * 8 + m + 4) * 36 + cin * 9 + t];   // co = 2g+1 (o = m+4)
        }
        sw2[2 * d]     = lo;
        sw2[2 * d + 1] = hi;
    }

    // ---- input tile, zero-padded halo, stored PRE-PACKED (v,v) ----
    for (int d = tid; d < SX_PAIRS; d += NTHREADS) {
        int cin = d / (SROWS * SCOLS);
        int rem = d - cin * (SROWS * SCOLS);
        int r   = rem / SCOLS;
        int c   = rem - r * SCOLS;
        int gr  = h0 - 1 + r;
        int gc  = w0 - 1 + c;
        float v = 0.f;
        if ((unsigned)gr < (unsigned)HH && (unsigned)gc < (unsigned)WW)
            v = x[((b * CIN + cin) * HH + gr) * WW + gc];
        sxp[d] = pack2(v);
    }
    __syncthreads();

    const int lane = tid & 31;
    const int wid  = tid >> 5;
    const int Q0   = wid * NQ;    // first (block-local) quad-row of this warp

    // 32-bit element-offset base for this thread's output columns
    const unsigned obase_bw = (unsigned)(b * COUT) * (HH * WW) + (unsigned)(w0 + 2 * lane);

    #pragma unroll
    for (int g = 0; g < 4; ++g) {
        const int gy = g >> 1;
        const int gx = g & 1;

        ull acc[4][NQ];
        #pragma unroll
        for (int m = 0; m < 4; ++m)
            #pragma unroll
            for (int q = 0; q < NQ; ++q)
                acc[m][q] = 0ull;

        const float* sw2g = sw2 + g * (CIN * 4 * 2 * WPAIR_STRIDE);
        if (gx == 0) do_group<0>(sxp, sw2g, acc, 2 * Q0 + gy, lane);
        else         do_group<1>(sxp, sw2g, acc, 2 * Q0 + gy, lane);

        // ---- store this g's outputs (co = 2g lo, co = 2g+1 hi) ----
        #pragma unroll
        for (int q = 0; q < NQ; ++q) {
            #pragma unroll
            for (int i = 0; i < 2; ++i) {
                float lo0, hi0, lo1, hi1;
                unpack2(acc[2 * i    ][q], lo0, hi0);   // j = 0
                unpack2(acc[2 * i + 1][q], lo1, hi1);   // j = 1
                const unsigned row = (unsigned)(h0 + 2 * (Q0 + q) + i);
                unsigned o0 = obase_bw + (unsigned)(2 * g) * (HH * WW) + row * WW;
                unsigned o1 = o0 + (unsigned)(HH * WW);
                *reinterpret_cast<float2*>(&out[o0]) = make_float2(lo0, lo1);
                *reinterpret_cast<float2*>(&out[o1]) = make_float2(hi0, hi1);
            }
        }
    }
}

extern "C" void kernel_launch(void* const* d_in, const int* in_sizes, int n_in,
                              void* d_out, int out_size)
{
    const float* x  = (const float*)d_in[0];
    const float* wt = (const float*)d_in[1];
    float* out      = (float*)d_out;

    int B = in_sizes[0] / (CIN * HH * WW);   // 8

    dim3 grid(WW / TILE_W, HH / TILE_H, B);  // (8, 32, 8) = 2048 blocks
    periodic_conv_kernel<<<grid, NTHREADS>>>(x, wt, out);
}

// round 8
// speedup vs baseline: 1.3008x; 1.3008x over previous
#include <cuda_runtime.h>

// PeriodicConvOp collapsed to a spatially-parameterized 3x3 conv:
//   out[b, co, 2hp+i, 2wp+j] =
//     sum_{cin,ky,kx} W[(g*8+o)*36 + cin*9 + ky*3 + kx]
//                     * x[b, cin, 2hp+gy+ky-1, 2wp+gx+kx-1]
//   g = co>>1, gy = g>>1, gx = g&1, o = ((co&1)<<2) | m, m = 2i+j
//
// Round-7: R5's sequential-g phases (small live set) + R4's FLOAT smem tile.
// R5 regression root-cause: 43KB smem x 5 blocks = 215KB carveout left ~13KB
// L1 -> DRAM traffic x6. Back to 24KB smem; pack (v,v) pairs in registers.

#define CIN   4
#define COUT  8
#define HH    512
#define WW    512

#define TILE_H 16          // output rows per block
#define TILE_W 64          // output cols per block
#define SROWS  (TILE_H + 2)   // 18 input rows  (h0-1 .. h0+16)
#define SCOLS  (TILE_W + 2)   // 66 input cols  (w0-1 .. w0+64)
#define SX_FLOATS (CIN * SROWS * SCOLS)     // 4752 floats (19008 B)

#define WPAIR_STRIDE 10    // float2 slots per (g,cin,m): 9 taps + 1 pad
#define SW_FLOATS (4 * CIN * 4 * WPAIR_STRIDE * 2)   // 1280 floats (5120 B)

#define NQ 2               // quad-rows per warp
#define NTHREADS 128       // 4 warps; block = 8 quad rows x 32 quad cols

typedef unsigned long long ull;

__device__ __forceinline__ ull pack2(float v) {
    ull r; asm("mov.b64 %0, {%1, %1};" : "=l"(r) : "f"(v)); return r;
}
__device__ __forceinline__ void unpack2(ull v, float& lo, float& hi) {
    asm("mov.b64 {%0, %1}, %2;" : "=f"(lo), "=f"(hi) : "l"(v));
}
__device__ __forceinline__ void fma2(ull& d, ull a, ull b) {
    asm("fma.rn.f32x2 %0, %1, %2, %0;" : "+l"(d) : "l"(a), "l"(b));
}

// One group phase. GX templated: window column select is compile-time.
template<int GX>
__device__ __forceinline__ void do_group(
    const float* __restrict__ sx,     // float input tile
    const float* __restrict__ sw2g,   // weights for this g: [cin][m][pairs]
    ull (&acc)[4][NQ],                // [m][q]
    int baserow,                      // 2*Q0 + gy
    int lane)
{
    #pragma unroll
    for (int cin = 0; cin < CIN; ++cin) {
        const float* bp = sx + cin * (SROWS * SCOLS) + baserow * SCOLS + 2 * lane;

        // 5 rows x 3 packed cols; win[2q+ky][kx] = pack2(x[row][2l+GX+kx])
        ull win[5][3];
        #pragma unroll
        for (int rr = 0; rr < 5; ++rr) {
            const float* rowp = bp + rr * SCOLS;
            float2 p01 = *reinterpret_cast<const float2*>(rowp);
            float2 p23 = *reinterpret_cast<const float2*>(rowp + 2);
            if (GX == 0) {
                win[rr][0] = pack2(p01.x);
                win[rr][1] = pack2(p01.y);
                win[rr][2] = pack2(p23.x);
            } else {
                win[rr][0] = pack2(p01.y);
                win[rr][1] = pack2(p23.x);
                win[rr][2] = pack2(p23.y);
            }
        }

        #pragma unroll
        for (int m = 0; m < 4; ++m) {
            const ulonglong2* wp = reinterpret_cast<const ulonglong2*>(
                sw2g + (cin * 4 + m) * (2 * WPAIR_STRIDE));
            ull w[10];
            #pragma unroll
            for (int t = 0; t < 5; ++t) {
                ulonglong2 v = wp[t];
                w[2 * t] = v.x; w[2 * t + 1] = v.y;
            }
            #pragma unroll
            for (int q = 0; q < NQ; ++q)
                #pragma unroll
                for (int ky = 0; ky < 3; ++ky)
                    #pragma unroll
                    for (int kx = 0; kx < 3; ++kx)
                        fma2(acc[m][q], w[ky * 3 + kx], win[2 * q + ky][kx]);
        }
    }
}

__global__ void __launch_bounds__(NTHREADS)
periodic_conv_kernel(const float* __restrict__ x,
                     const float* __restrict__ wt,
                     float* __restrict__ out)
{
    __shared__ __align__(16) float sx[SX_FLOATS];
    __shared__ __align__(16) float sw2[SW_FLOATS];

    const int b   = blockIdx.z;
    const int h0  = blockIdx.y * TILE_H;
    const int w0  = blockIdx.x * TILE_W;
    const int tid = threadIdx.x;

    // ---- weights: channel-pair interleave. entry d = ((g*4+cin)*4+m)*10+t ----
    for (int d = tid; d < 4 * CIN * 4 * WPAIR_STRIDE; d += NTHREADS) {
        int t   = d % WPAIR_STRIDE;
        int r   = d / WPAIR_STRIDE;
        int m   = r & 3;  r >>= 2;
        int cin = r & 3;
        int g   = r >> 2;
        float lo = 0.f, hi = 0.f;
        if (t < 9) {
            lo = wt[(g * 8 + m    ) * 36 + cin * 9 + t];   // co = 2g   (o = m)
            hi = wt[(g * 8 + m + 4) * 36 + cin * 9 + t];   // co = 2g+1 (o = m+4)
        }
        sw2[2 * d]     = lo;
        sw2[2 * d + 1] = hi;
    }

    // ---- input tile with zero-padded halo (origin: h0-1, w0-1) ----
    for (int d = tid; d < SX_FLOATS; d += NTHREADS) {
        int cin = d / (SROWS * SCOLS);
        int rem = d - cin * (SROWS * SCOLS);
        int r   = rem / SCOLS;
        int c   = rem - r * SCOLS;
        int gr  = h0 - 1 + r;
        int gc  = w0 - 1 + c;
        float v = 0.f;
        if ((unsigned)gr < (unsigned)HH && (unsigned)gc < (unsigned)WW)
            v = x[((b * CIN + cin) * HH + gr) * WW + gc];
        sx[d] = v;
    }
    __syncthreads();

    const int lane = tid & 31;
    const int wid  = tid >> 5;
    const int Q0   = wid * NQ;    // first (block-local) quad-row of this warp

    // 32-bit element-offset base for this thread's output columns
    const unsigned obase_bw = (unsigned)(b * COUT) * (HH * WW) + (unsigned)(w0 + 2 * lane);

    #pragma unroll
    for (int g = 0; g < 4; ++g) {
        const int gy = g >> 1;
        const int gx = g & 1;

        ull acc[4][NQ];
        #pragma unroll
        for (int m = 0; m < 4; ++m)
            #pragma unroll
            for (int q = 0; q < NQ; ++q)
                acc[m][q] = 0ull;

        const float* sw2g = sw2 + g * (CIN * 4 * 2 * WPAIR_STRIDE);
        if (gx == 0) do_group<0>(sx, sw2g, acc, 2 * Q0 + gy, lane);
        else         do_group<1>(sx, sw2g, acc, 2 * Q0 + gy, lane);

        // ---- store this g's outputs (co = 2g lo, co = 2g+1 hi) ----
        #pragma unroll
        for (int q = 0; q < NQ; ++q) {
            #pragma unroll
            for (int i = 0; i < 2; ++i) {
                float lo0, hi0, lo1, hi1;
                unpack2(acc[2 * i    ][q], lo0, hi0);   // j = 0
                unpack2(acc[2 * i + 1][q], lo1, hi1);   // j = 1
                const unsigned row = (unsigned)(h0 + 2 * (Q0 + q) + i);
                unsigned o0 = obase_bw + (unsigned)(2 * g) * (HH * WW) + row * WW;
                unsigned o1 = o0 + (unsigned)(HH * WW);
                *reinterpret_cast<float2*>(&out[o0]) = make_float2(lo0, lo1);
                *reinterpret_cast<float2*>(&out[o1]) = make_float2(hi0, hi1);
            }
        }
    }
}

extern "C" void kernel_launch(void* const* d_in, const int* in_sizes, int n_in,
                              void* d_out, int out_size)
{
    const float* x  = (const float*)d_in[0];
    const float* wt = (const float*)d_in[1];
    float* out      = (float*)d_out;

    int B = in_sizes[0] / (CIN * HH * WW);   // 8

    dim3 grid(WW / TILE_W, HH / TILE_H, B);  // (8, 32, 8) = 2048 blocks
    periodic_conv_kernel<<<grid, NTHREADS>>>(x, wt, out);
}